// round 6
// baseline (speedup 1.0000x reference)
#include <cuda_runtime.h>
#include <math.h>

#define BATCH    64
#define IN_SIZE  1024
#define IN_DIM   256
#define HEADS    4
#define OUT_SIZE 64
#define OUT_DIM  256
#define NMAT     (BATCH * HEADS)     /* 256 */
#define HID      (HEADS * IN_DIM)    /* 1024 */
#define MAX_ITER 10

// ---------------------------------------------------------------------------
// Scratch (no dynamic allocation allowed)
// ---------------------------------------------------------------------------
__device__ float g_K[(size_t)NMAT * IN_SIZE * OUT_SIZE];   // 64 MB: exp(x·Wᵀ/eps), [n][s][o]
__device__ float g_u[(size_t)NMAT * IN_SIZE];              // final sinkhorn u
__device__ float g_v[(size_t)NMAT * OUT_SIZE];             // final sinkhorn v
__device__ float g_att[(size_t)BATCH * OUT_SIZE * HID];    // 16 MB: pre-linear activations

// ---------------------------------------------------------------------------
// Kernel 1: K[n][s][o] = exp( (x[b,s,:]·W[h,o,:]) * 10 ),  n = b*4+h
// Tiled SGEMM: BM=128(s) x BN=64(o) x BK=32(d), 256 threads, 8x4 per thread.
// ---------------------------------------------------------------------------
__global__ __launch_bounds__(256) void gemm_k_kernel(const float* __restrict__ x,
                                                     const float* __restrict__ W) {
    const int BM = 128, BK = 32;
    __shared__ float As[BK][BM + 1];      // [k][m]
    __shared__ float Bs[BK][OUT_SIZE + 1];// [k][o]

    int n_id = blockIdx.y;
    int b = n_id >> 2, h = n_id & 3;
    int s0 = blockIdx.x * BM;
    const float* xg = x + ((size_t)b * IN_SIZE + s0) * IN_DIM;
    const float* wg = W + (size_t)h * OUT_SIZE * IN_DIM;

    int tid  = threadIdx.x;
    int trow = tid >> 4;        // 0..15 -> m = trow*8 + i
    int tcol = tid & 15;        // 0..15 -> o = tcol + 16*j
    int lrow = tid >> 3;        // 0..31
    int lcol = (tid & 7) * 4;   // 0..28

    float acc[8][4];
    #pragma unroll
    for (int i = 0; i < 8; ++i)
        #pragma unroll
        for (int j = 0; j < 4; ++j) acc[i][j] = 0.f;

    for (int k0 = 0; k0 < IN_DIM; k0 += BK) {
        #pragma unroll
        for (int p = 0; p < 4; ++p) {
            float4 v = *(const float4*)(xg + (size_t)(lrow + p * 32) * IN_DIM + k0 + lcol);
            As[lcol + 0][lrow + p * 32] = v.x;
            As[lcol + 1][lrow + p * 32] = v.y;
            As[lcol + 2][lrow + p * 32] = v.z;
            As[lcol + 3][lrow + p * 32] = v.w;
        }
        #pragma unroll
        for (int p = 0; p < 2; ++p) {
            float4 v = *(const float4*)(wg + (size_t)(lrow + p * 32) * IN_DIM + k0 + lcol);
            Bs[lcol + 0][lrow + p * 32] = v.x;
            Bs[lcol + 1][lrow + p * 32] = v.y;
            Bs[lcol + 2][lrow + p * 32] = v.z;
            Bs[lcol + 3][lrow + p * 32] = v.w;
        }
        __syncthreads();
        #pragma unroll
        for (int k = 0; k < BK; ++k) {
            float a[8], bb[4];
            #pragma unroll
            for (int i = 0; i < 8; ++i) a[i] = As[k][trow * 8 + i];
            #pragma unroll
            for (int j = 0; j < 4; ++j) bb[j] = Bs[k][tcol + 16 * j];
            #pragma unroll
            for (int i = 0; i < 8; ++i)
                #pragma unroll
                for (int j = 0; j < 4; ++j) acc[i][j] = fmaf(a[i], bb[j], acc[i][j]);
        }
        __syncthreads();
    }

    float* kg = g_K + ((size_t)n_id * IN_SIZE + s0) * OUT_SIZE;
    #pragma unroll
    for (int i = 0; i < 8; ++i) {
        int s = trow * 8 + i;
        #pragma unroll
        for (int j = 0; j < 4; ++j)
            kg[(size_t)s * OUT_SIZE + tcol + 16 * j] = expf(acc[i][j] * 10.0f);
    }
}

// ---------------------------------------------------------------------------
// Kernel 2: Sinkhorn, one CTA per n (256 CTAs, 1024 threads = 32 warps).
// Fused iteration: one pass over K per iteration computes u then accumulates
// the new-v partials from the same K registers. u/v written out at the end.
// Mask is read as int32 (bool input widened by the harness; a nonzero test is
// also correct if it was widened to float32, since 1.0f != 0 bitwise).
// ---------------------------------------------------------------------------
__global__ __launch_bounds__(1024) void sinkhorn_kernel(const int* __restrict__ mask) {
    int n = blockIdx.x;
    int b = n >> 2;
    __shared__ float sm_mask[IN_SIZE];
    __shared__ float sm_u[IN_SIZE];
    __shared__ float sm_v[OUT_SIZE];
    __shared__ float sm_vacc[32][OUT_SIZE];
    __shared__ float sm_red[32];
    __shared__ float sm_a;

    int tid = threadIdx.x, lane = tid & 31, wid = tid >> 5;

    float m = (mask[(size_t)b * IN_SIZE + tid] != 0) ? 1.0f : 0.0f;
    sm_mask[tid] = m;
    float s = m;
    #pragma unroll
    for (int off = 16; off; off >>= 1) s += __shfl_xor_sync(0xffffffffu, s, off);
    if (lane == 0) sm_red[wid] = s;
    if (tid < OUT_SIZE) sm_v[tid] = 1.0f;
    __syncthreads();
    if (tid == 0) {
        float t = 0.f;
        #pragma unroll
        for (int w = 0; w < 32; ++w) t += sm_red[w];
        sm_a = (float)OUT_SIZE / t;
    }
    __syncthreads();
    float a = sm_a;

    const float* Kn = g_K + (size_t)n * IN_SIZE * OUT_SIZE;
    int o0 = lane * 2;     // each lane owns 2 o-columns
    int r0 = wid * 32;     // each warp owns 32 rows

    for (int it = 0; it < MAX_ITER; ++it) {
        float v0 = sm_v[o0], v1 = sm_v[o0 + 1];
        float va0 = 0.f, va1 = 0.f;
        #pragma unroll
        for (int rr = 0; rr < 32; rr += 4) {
            int r = r0 + rr;
            const float* base = Kn + (size_t)r * OUT_SIZE + o0;
            float2 k0 = *(const float2*)(base);
            float2 k1 = *(const float2*)(base + OUT_SIZE);
            float2 k2 = *(const float2*)(base + 2 * OUT_SIZE);
            float2 k3 = *(const float2*)(base + 3 * OUT_SIZE);
            float p0 = fmaf(k0.y, v1, k0.x * v0);
            float p1 = fmaf(k1.y, v1, k1.x * v0);
            float p2 = fmaf(k2.y, v1, k2.x * v0);
            float p3 = fmaf(k3.y, v1, k3.x * v0);
            #pragma unroll
            for (int off = 16; off; off >>= 1) {
                p0 += __shfl_xor_sync(0xffffffffu, p0, off);
                p1 += __shfl_xor_sync(0xffffffffu, p1, off);
                p2 += __shfl_xor_sync(0xffffffffu, p2, off);
                p3 += __shfl_xor_sync(0xffffffffu, p3, off);
            }
            float u0 = sm_mask[r + 0] * (a / p0);
            float u1 = sm_mask[r + 1] * (a / p1);
            float u2 = sm_mask[r + 2] * (a / p2);
            float u3 = sm_mask[r + 3] * (a / p3);
            if (lane == 0) {
                sm_u[r + 0] = u0; sm_u[r + 1] = u1;
                sm_u[r + 2] = u2; sm_u[r + 3] = u3;
            }
            va0 = fmaf(u0, k0.x, va0); va1 = fmaf(u0, k0.y, va1);
            va0 = fmaf(u1, k1.x, va0); va1 = fmaf(u1, k1.y, va1);
            va0 = fmaf(u2, k2.x, va0); va1 = fmaf(u2, k2.y, va1);
            va0 = fmaf(u3, k3.x, va0); va1 = fmaf(u3, k3.y, va1);
        }
        sm_vacc[wid][o0]     = va0;
        sm_vacc[wid][o0 + 1] = va1;
        __syncthreads();
        if (tid < OUT_SIZE) {
            float t = 0.f;
            #pragma unroll
            for (int w = 0; w < 32; ++w) t += sm_vacc[w][tid];
            sm_v[tid] = 1.0f / t;
        }
        __syncthreads();
    }

    g_u[(size_t)n * IN_SIZE + tid] = sm_u[tid];
    if (tid < OUT_SIZE) g_v[(size_t)n * OUT_SIZE + tid] = sm_v[tid];
}

// ---------------------------------------------------------------------------
// Kernel 3: att[b,o,h*256+d] = v[n,o] * sum_s (u[n,s]*K[n,s,o]) * x[b,s,d]
// Per CTA: one n, 128 d-cols. BM=64(o) x BN=128(d) x BK=64(s), 256 threads.
// ---------------------------------------------------------------------------
__global__ __launch_bounds__(256) void attn_kernel(const float* __restrict__ x) {
    const int BN = 128, BK = 64;
    __shared__ float Ks[BK][OUT_SIZE];   // [s][o], u-scaled (16 KB)
    __shared__ float Xs[BK][BN];         // [s][d]          (32 KB)

    int n = blockIdx.y;
    int b = n >> 2, h = n & 3;
    int d0 = blockIdx.x * BN;
    int tid = threadIdx.x;
    int trow = tid >> 4;    // o = trow*4 + i
    int tcol = tid & 15;    // d = tcol + 16*j

    const float* Kn = g_K + (size_t)n * IN_SIZE * OUT_SIZE;
    const float* un = g_u + (size_t)n * IN_SIZE;
    const float* xg = x + (size_t)b * IN_SIZE * IN_DIM + d0;

    float acc[4][8];
    #pragma unroll
    for (int i = 0; i < 4; ++i)
        #pragma unroll
        for (int j = 0; j < 8; ++j) acc[i][j] = 0.f;

    for (int s0 = 0; s0 < IN_SIZE; s0 += BK) {
        #pragma unroll
        for (int p = 0; p < 4; ++p) {
            int r = (tid >> 4) + p * 16;
            float uu = un[s0 + r];
            int c = (tid & 15) * 4;
            float4 kv = *(const float4*)(Kn + (size_t)(s0 + r) * OUT_SIZE + c);
            kv.x *= uu; kv.y *= uu; kv.z *= uu; kv.w *= uu;
            *(float4*)&Ks[r][c] = kv;
        }
        #pragma unroll
        for (int p = 0; p < 8; ++p) {
            int r = (tid >> 5) + p * 8;
            int c = (tid & 31) * 4;
            float4 xv = *(const float4*)(xg + (size_t)(s0 + r) * IN_DIM + c);
            *(float4*)&Xs[r][c] = xv;
        }
        __syncthreads();
        #pragma unroll
        for (int k = 0; k < BK; ++k) {
            float av[4], bv[8];
            #pragma unroll
            for (int i = 0; i < 4; ++i) av[i] = Ks[k][trow * 4 + i];
            #pragma unroll
            for (int j = 0; j < 8; ++j) bv[j] = Xs[k][tcol + 16 * j];
            #pragma unroll
            for (int i = 0; i < 4; ++i)
                #pragma unroll
                for (int j = 0; j < 8; ++j) acc[i][j] = fmaf(av[i], bv[j], acc[i][j]);
        }
        __syncthreads();
    }

    const float* vn = g_v + (size_t)n * OUT_SIZE;
    #pragma unroll
    for (int i = 0; i < 4; ++i) {
        int o = trow * 4 + i;
        float vv = vn[o];
        float* og = g_att + (size_t)(b * OUT_SIZE + o) * HID + (size_t)h * IN_DIM + d0;
        #pragma unroll
        for (int j = 0; j < 8; ++j) og[tcol + 16 * j] = vv * acc[i][j];
    }
}

// ---------------------------------------------------------------------------
// Kernel 4: out[m, :] = relu(att[m, :] @ lin_wᵀ + lin_b), m = b*64+o (4096 rows)
// BM=64 x BN=64 x BK=32, 256 threads, 4x4 per thread.
// ---------------------------------------------------------------------------
__global__ __launch_bounds__(256) void linear_kernel(const float* __restrict__ lw,
                                                     const float* __restrict__ lb,
                                                     float* __restrict__ out) {
    const int BM = 64, BN = 64, BK = 32;
    __shared__ float As[BK][BM + 1];
    __shared__ float Bs[BK][BN + 1];

    int m0 = blockIdx.x * BM;
    int n0 = blockIdx.y * BN;
    int tid = threadIdx.x;
    int trow = tid >> 4, tcol = tid & 15;
    int lrow = tid >> 3;
    int lcol = (tid & 7) * 4;

    float acc[4][4];
    #pragma unroll
    for (int i = 0; i < 4; ++i)
        #pragma unroll
        for (int j = 0; j < 4; ++j) acc[i][j] = 0.f;

    for (int k0 = 0; k0 < HID; k0 += BK) {
        #pragma unroll
        for (int p = 0; p < 2; ++p) {
            float4 v = *(const float4*)(g_att + (size_t)(m0 + lrow + p * 32) * HID + k0 + lcol);
            As[lcol + 0][lrow + p * 32] = v.x;
            As[lcol + 1][lrow + p * 32] = v.y;
            As[lcol + 2][lrow + p * 32] = v.z;
            As[lcol + 3][lrow + p * 32] = v.w;
            float4 w = *(const float4*)(lw + (size_t)(n0 + lrow + p * 32) * HID + k0 + lcol);
            Bs[lcol + 0][lrow + p * 32] = w.x;
            Bs[lcol + 1][lrow + p * 32] = w.y;
            Bs[lcol + 2][lrow + p * 32] = w.z;
            Bs[lcol + 3][lrow + p * 32] = w.w;
        }
        __syncthreads();
        #pragma unroll
        for (int k = 0; k < BK; ++k) {
            float a[4], bb[4];
            #pragma unroll
            for (int i = 0; i < 4; ++i) a[i] = As[k][trow * 4 + i];
            #pragma unroll
            for (int j = 0; j < 4; ++j) bb[j] = Bs[k][tcol + 16 * j];
            #pragma unroll
            for (int i = 0; i < 4; ++i)
                #pragma unroll
                for (int j = 0; j < 4; ++j) acc[i][j] = fmaf(a[i], bb[j], acc[i][j]);
        }
        __syncthreads();
    }

    #pragma unroll
    for (int i = 0; i < 4; ++i) {
        int m = m0 + trow * 4 + i;
        #pragma unroll
        for (int j = 0; j < 4; ++j) {
            int nn = n0 + tcol + 16 * j;
            float r = acc[i][j] + lb[nn];
            out[(size_t)m * OUT_DIM + nn] = r > 0.f ? r : 0.f;
        }
    }
}

// ---------------------------------------------------------------------------
// Launch: x, target_mask(bool->int32/f32), W, lin_w, lin_b -> out [64,64,256] f32
// ---------------------------------------------------------------------------
extern "C" void kernel_launch(void* const* d_in, const int* in_sizes, int n_in,
                              void* d_out, int out_size) {
    const float* x    = (const float*)d_in[0];
    const int*   mask = (const int*)d_in[1];
    const float* W    = (const float*)d_in[2];
    const float* lw   = (const float*)d_in[3];
    const float* lb   = (const float*)d_in[4];
    float*       out  = (float*)d_out;

    gemm_k_kernel<<<dim3(IN_SIZE / 128, NMAT), 256>>>(x, W);
    sinkhorn_kernel<<<NMAT, 1024>>>(mask);
    attn_kernel<<<dim3(IN_DIM / 128, NMAT), 256>>>(x);
    linear_kernel<<<dim3(BATCH * OUT_SIZE / 64, OUT_DIM / 64), 256>>>(lw, lb, out);
}

// round 8
// speedup vs baseline: 1.5523x; 1.5523x over previous
#include <cuda_runtime.h>
#include <cuda_bf16.h>
#include <math.h>
#include <stdint.h>

#define BATCH    64
#define IN_SIZE  1024
#define IN_DIM   256
#define HEADS    4
#define OUT_SIZE 64
#define OUT_DIM  256
#define NMAT     (BATCH * HEADS)     /* 256 */
#define HID      (HEADS * IN_DIM)    /* 1024 */
#define MAX_ITER 10

// ---------------------------------------------------------------------------
// Scratch
// ---------------------------------------------------------------------------
__device__ float g_K[(size_t)NMAT * IN_SIZE * OUT_SIZE];        // 64 MB [n][s][o]
__device__ float g_u[(size_t)NMAT * IN_SIZE];
__device__ float g_v[(size_t)NMAT * OUT_SIZE];
__device__ float g_att[(size_t)BATCH * OUT_SIZE * HID];         // 16 MB
__device__ __nv_bfloat16 g_xT_hi[(size_t)BATCH * IN_DIM * IN_SIZE];   // [b][d][s]
__device__ __nv_bfloat16 g_xT_lo[(size_t)BATCH * IN_DIM * IN_SIZE];
__device__ __nv_bfloat16 g_kT_hi[(size_t)NMAT * OUT_SIZE * IN_SIZE];  // [n][o][s]
__device__ __nv_bfloat16 g_kT_lo[(size_t)NMAT * OUT_SIZE * IN_SIZE];

// ---------------------------------------------------------------------------
// Warp MMA helpers (plain PTX, valid on base sm_100 target)
// ---------------------------------------------------------------------------
__device__ __forceinline__ uint32_t smem_u32(const void* p) {
    uint32_t a;
    asm("{ .reg .u64 t; cvta.to.shared.u64 t, %1; cvt.u32.u64 %0, t; }" : "=r"(a) : "l"(p));
    return a;
}
__device__ __forceinline__ void ldsm4(uint32_t* r, uint32_t a) {
    asm volatile("ldmatrix.sync.aligned.m8n8.x4.shared.b16 {%0,%1,%2,%3}, [%4];"
        : "=r"(r[0]), "=r"(r[1]), "=r"(r[2]), "=r"(r[3]) : "r"(a));
}
__device__ __forceinline__ void ldsm2(uint32_t* r, uint32_t a) {
    asm volatile("ldmatrix.sync.aligned.m8n8.x2.shared.b16 {%0,%1}, [%2];"
        : "=r"(r[0]), "=r"(r[1]) : "r"(a));
}
__device__ __forceinline__ void mma16816(float* c, const uint32_t* a, const uint32_t* b) {
    asm volatile(
        "mma.sync.aligned.m16n8k16.row.col.f32.bf16.bf16.f32 "
        "{%0,%1,%2,%3}, {%4,%5,%6,%7}, {%8,%9}, {%0,%1,%2,%3};"
        : "+f"(c[0]), "+f"(c[1]), "+f"(c[2]), "+f"(c[3])
        : "r"(a[0]), "r"(a[1]), "r"(a[2]), "r"(a[3]), "r"(b[0]), "r"(b[1]));
}
__device__ __forceinline__ uint32_t pack2(__nv_bfloat16 a, __nv_bfloat16 b) {
    uint16_t ua = *(uint16_t*)&a, ub = *(uint16_t*)&b;
    return (uint32_t)ua | ((uint32_t)ub << 16);
}
__device__ __forceinline__ void split2(float f, __nv_bfloat16& h, __nv_bfloat16& l) {
    h = __float2bfloat16(f);
    l = __float2bfloat16(f - __bfloat162float(h));
}

// Padded bf16 SMEM tiles: row stride 72 elems (144 B = 9*16 -> ldmatrix rows
// 16B-aligned, no 128B-stride bank pathologies).
#define RS 72
// SMEM layout (bytes): Ah[128*72] | Al | Bh[64*72] | Bl
#define OFF_AH 0
#define OFF_AL (128 * RS * 2)
#define OFF_BH (2 * 128 * RS * 2)
#define OFF_BL (2 * 128 * RS * 2 + 64 * RS * 2)
#define DSMEM_BYTES (2 * 128 * RS * 2 + 2 * 64 * RS * 2)   /* 55296 */

// ---------------------------------------------------------------------------
// Kernel 1: K = exp(10 * x·Wᵀ), bf16 split-2 HMMA.
// CTA = (s-tile 128, n). M=128(s) N=64(o) K=256(d), 4 chunks of 64.
// 8 warps = 4(m) x 2(n); warp tile 32x32 = 2x4 m16n8k16 frags.
// ---------------------------------------------------------------------------
__global__ __launch_bounds__(256) void gemm_k_mma(const float* __restrict__ x,
                                                  const float* __restrict__ W) {
    extern __shared__ char dyn[];
    __nv_bfloat16* Ah = (__nv_bfloat16*)(dyn + OFF_AH);
    __nv_bfloat16* Al = (__nv_bfloat16*)(dyn + OFF_AL);
    __nv_bfloat16* Bh = (__nv_bfloat16*)(dyn + OFF_BH);
    __nv_bfloat16* Bl = (__nv_bfloat16*)(dyn + OFF_BL);

    int tid = threadIdx.x, lane = tid & 31, wid = tid >> 5;
    int wm = wid & 3, wn = wid >> 2;
    int n = blockIdx.y, b = n >> 2, h = n & 3;
    int s0 = blockIdx.x * 128;
    const float* xg = x + ((size_t)b * IN_SIZE + s0) * IN_DIM;
    const float* wg = W + (size_t)h * OUT_SIZE * IN_DIM;

    // ldmatrix base addresses (bytes), per-warp
    uint32_t aBaseH = smem_u32(Ah) + ((wm * 32 + (lane & 15)) * RS + (lane >> 4) * 8) * 2;
    uint32_t aBaseL = aBaseH + (OFF_AL - OFF_AH);
    uint32_t bBaseH = smem_u32(Bh) + ((wn * 32 + (lane & 7)) * RS + ((lane >> 3) & 1) * 8) * 2;
    uint32_t bBaseL = bBaseH + (OFF_BL - OFF_BH);

    float c[2][4][4];
    #pragma unroll
    for (int f = 0; f < 2; ++f)
        #pragma unroll
        for (int g = 0; g < 4; ++g)
            #pragma unroll
            for (int q = 0; q < 4; ++q) c[f][g][q] = 0.f;

    for (int ch = 0; ch < 4; ++ch) {
        int d0 = ch * 64;
        // A: 128 x 64 fp32 -> hi/lo bf16 padded
        #pragma unroll
        for (int i = 0; i < 8; ++i) {
            int vi = i * 256 + tid;
            int row = vi >> 4, c4 = (vi & 15) * 4;
            float4 v = *(const float4*)(xg + (size_t)row * IN_DIM + d0 + c4);
            __nv_bfloat16 h0, h1, h2, h3, l0, l1, l2, l3;
            split2(v.x, h0, l0); split2(v.y, h1, l1);
            split2(v.z, h2, l2); split2(v.w, h3, l3);
            int off = row * RS + c4;
            *(uint2*)(Ah + off) = make_uint2(pack2(h0, h1), pack2(h2, h3));
            *(uint2*)(Al + off) = make_uint2(pack2(l0, l1), pack2(l2, l3));
        }
        // B: 64 x 64
        #pragma unroll
        for (int i = 0; i < 4; ++i) {
            int vi = i * 256 + tid;
            int row = vi >> 4, c4 = (vi & 15) * 4;
            float4 v = *(const float4*)(wg + (size_t)row * IN_DIM + d0 + c4);
            __nv_bfloat16 h0, h1, h2, h3, l0, l1, l2, l3;
            split2(v.x, h0, l0); split2(v.y, h1, l1);
            split2(v.z, h2, l2); split2(v.w, h3, l3);
            int off = row * RS + c4;
            *(uint2*)(Bh + off) = make_uint2(pack2(h0, h1), pack2(h2, h3));
            *(uint2*)(Bl + off) = make_uint2(pack2(l0, l1), pack2(l2, l3));
        }
        __syncthreads();
        #pragma unroll
        for (int ks = 0; ks < 4; ++ks) {
            uint32_t ah[2][4], al[2][4], bh[4][2], bl[4][2];
            #pragma unroll
            for (int f = 0; f < 2; ++f) {
                uint32_t o = (uint32_t)(f * 16 * RS + ks * 16) * 2;
                ldsm4(ah[f], aBaseH + o);
                ldsm4(al[f], aBaseL + o);
            }
            #pragma unroll
            for (int g = 0; g < 4; ++g) {
                uint32_t o = (uint32_t)(g * 8 * RS + ks * 16) * 2;
                ldsm2(bh[g], bBaseH + o);
                ldsm2(bl[g], bBaseL + o);
            }
            #pragma unroll
            for (int f = 0; f < 2; ++f)
                #pragma unroll
                for (int g = 0; g < 4; ++g) {
                    mma16816(c[f][g], ah[f], bh[g]);
                    mma16816(c[f][g], ah[f], bl[g]);
                    mma16816(c[f][g], al[f], bh[g]);
                }
        }
        __syncthreads();
    }

    // Epilogue: exp(10*acc) -> g_K[n][s][o]
    #pragma unroll
    for (int f = 0; f < 2; ++f) {
        int r0 = s0 + wm * 32 + f * 16 + (lane >> 2);
        #pragma unroll
        for (int g = 0; g < 4; ++g) {
            int o = wn * 32 + g * 8 + (lane & 3) * 2;
            float* p0 = g_K + ((size_t)n * IN_SIZE + r0) * OUT_SIZE + o;
            float* p1 = p0 + 8 * OUT_SIZE;
            float2 v0 = make_float2(expf(c[f][g][0] * 10.f), expf(c[f][g][1] * 10.f));
            float2 v1 = make_float2(expf(c[f][g][2] * 10.f), expf(c[f][g][3] * 10.f));
            *(float2*)p0 = v0;
            *(float2*)p1 = v1;
        }
    }
}

// ---------------------------------------------------------------------------
// Kernel 2: x[b][s][d] fp32 -> g_xT_hi/lo[b][d][s] bf16 (64x64 transpose)
// ---------------------------------------------------------------------------
__global__ __launch_bounds__(256) void xsplit_kernel(const float* __restrict__ x) {
    __shared__ float sm[64][65];
    int tid = threadIdx.x;
    int s0 = blockIdx.x * 64, d0 = blockIdx.y * 64, b = blockIdx.z;
    const float* xb = x + ((size_t)b * IN_SIZE + s0) * IN_DIM + d0;
    #pragma unroll
    for (int i = 0; i < 4; ++i) {
        int vi = i * 256 + tid;
        int rs = vi >> 4, c4 = (vi & 15) * 4;
        float4 v = *(const float4*)(xb + (size_t)rs * IN_DIM + c4);
        sm[rs][c4] = v.x; sm[rs][c4 + 1] = v.y; sm[rs][c4 + 2] = v.z; sm[rs][c4 + 3] = v.w;
    }
    __syncthreads();
    #pragma unroll
    for (int i = 0; i < 4; ++i) {
        int vi = i * 256 + tid;
        int rd = vi >> 4, s4 = (vi & 15) * 4;
        __nv_bfloat16 h[4], l[4];
        #pragma unroll
        for (int j = 0; j < 4; ++j) split2(sm[s4 + j][rd], h[j], l[j]);
        size_t off = ((size_t)b * IN_DIM + d0 + rd) * IN_SIZE + s0 + s4;
        *(uint2*)(g_xT_hi + off) = make_uint2(pack2(h[0], h[1]), pack2(h[2], h[3]));
        *(uint2*)(g_xT_lo + off) = make_uint2(pack2(l[0], l[1]), pack2(l[2], l[3]));
    }
}

// ---------------------------------------------------------------------------
// Kernel 3: Sinkhorn (one CTA per n, fused u/v pass over K per iteration)
// ---------------------------------------------------------------------------
__global__ __launch_bounds__(1024) void sinkhorn_kernel(const int* __restrict__ mask) {
    int n = blockIdx.x;
    int b = n >> 2;
    __shared__ float sm_mask[IN_SIZE];
    __shared__ float sm_u[IN_SIZE];
    __shared__ float sm_v[OUT_SIZE];
    __shared__ float sm_vacc[32][OUT_SIZE];
    __shared__ float sm_red[32];
    __shared__ float sm_a;

    int tid = threadIdx.x, lane = tid & 31, wid = tid >> 5;

    float m = (mask[(size_t)b * IN_SIZE + tid] != 0) ? 1.0f : 0.0f;
    sm_mask[tid] = m;
    float s = m;
    #pragma unroll
    for (int off = 16; off; off >>= 1) s += __shfl_xor_sync(0xffffffffu, s, off);
    if (lane == 0) sm_red[wid] = s;
    if (tid < OUT_SIZE) sm_v[tid] = 1.0f;
    __syncthreads();
    if (tid == 0) {
        float t = 0.f;
        #pragma unroll
        for (int w = 0; w < 32; ++w) t += sm_red[w];
        sm_a = (float)OUT_SIZE / t;
    }
    __syncthreads();
    float a = sm_a;

    const float* Kn = g_K + (size_t)n * IN_SIZE * OUT_SIZE;
    int o0 = lane * 2;
    int r0 = wid * 32;

    for (int it = 0; it < MAX_ITER; ++it) {
        float v0 = sm_v[o0], v1 = sm_v[o0 + 1];
        float va0 = 0.f, va1 = 0.f;
        #pragma unroll
        for (int rr = 0; rr < 32; rr += 4) {
            int r = r0 + rr;
            const float* base = Kn + (size_t)r * OUT_SIZE + o0;
            float2 k0 = *(const float2*)(base);
            float2 k1 = *(const float2*)(base + OUT_SIZE);
            float2 k2 = *(const float2*)(base + 2 * OUT_SIZE);
            float2 k3 = *(const float2*)(base + 3 * OUT_SIZE);
            float p0 = fmaf(k0.y, v1, k0.x * v0);
            float p1 = fmaf(k1.y, v1, k1.x * v0);
            float p2 = fmaf(k2.y, v1, k2.x * v0);
            float p3 = fmaf(k3.y, v1, k3.x * v0);
            #pragma unroll
            for (int off = 16; off; off >>= 1) {
                p0 += __shfl_xor_sync(0xffffffffu, p0, off);
                p1 += __shfl_xor_sync(0xffffffffu, p1, off);
                p2 += __shfl_xor_sync(0xffffffffu, p2, off);
                p3 += __shfl_xor_sync(0xffffffffu, p3, off);
            }
            float u0 = sm_mask[r + 0] * (a / p0);
            float u1 = sm_mask[r + 1] * (a / p1);
            float u2 = sm_mask[r + 2] * (a / p2);
            float u3 = sm_mask[r + 3] * (a / p3);
            if (lane == 0) {
                sm_u[r + 0] = u0; sm_u[r + 1] = u1;
                sm_u[r + 2] = u2; sm_u[r + 3] = u3;
            }
            va0 = fmaf(u0, k0.x, va0); va1 = fmaf(u0, k0.y, va1);
            va0 = fmaf(u1, k1.x, va0); va1 = fmaf(u1, k1.y, va1);
            va0 = fmaf(u2, k2.x, va0); va1 = fmaf(u2, k2.y, va1);
            va0 = fmaf(u3, k3.x, va0); va1 = fmaf(u3, k3.y, va1);
        }
        sm_vacc[wid][o0] = va0;
        sm_vacc[wid][o0 + 1] = va1;
        __syncthreads();
        if (tid < OUT_SIZE) {
            float t = 0.f;
            #pragma unroll
            for (int w = 0; w < 32; ++w) t += sm_vacc[w][tid];
            sm_v[tid] = 1.0f / t;
        }
        __syncthreads();
    }

    g_u[(size_t)n * IN_SIZE + tid] = sm_u[tid];
    if (tid < OUT_SIZE) g_v[(size_t)n * OUT_SIZE + tid] = sm_v[tid];
}

// ---------------------------------------------------------------------------
// Kernel 4: (u⊙K)ᵀ split: g_kT_hi/lo[n][o][s] bf16. 64(s)x64(o) tiles.
// ---------------------------------------------------------------------------
__global__ __launch_bounds__(256) void kut_kernel() {
    __shared__ float sm[64][65];
    int tid = threadIdx.x;
    int s0 = blockIdx.x * 64, n = blockIdx.y;
    const float* Kn = g_K + ((size_t)n * IN_SIZE + s0) * OUT_SIZE;
    const float* un = g_u + (size_t)n * IN_SIZE + s0;
    #pragma unroll
    for (int i = 0; i < 4; ++i) {
        int vi = i * 256 + tid;
        int rs = vi >> 4, o4 = (vi & 15) * 4;
        float u = un[rs];
        float4 v = *(const float4*)(Kn + (size_t)rs * OUT_SIZE + o4);
        sm[rs][o4] = v.x * u; sm[rs][o4 + 1] = v.y * u;
        sm[rs][o4 + 2] = v.z * u; sm[rs][o4 + 3] = v.w * u;
    }
    __syncthreads();
    #pragma unroll
    for (int i = 0; i < 4; ++i) {
        int vi = i * 256 + tid;
        int ro = vi >> 4, s4 = (vi & 15) * 4;
        __nv_bfloat16 h[4], l[4];
        #pragma unroll
        for (int j = 0; j < 4; ++j) split2(sm[s4 + j][ro], h[j], l[j]);
        size_t off = ((size_t)n * OUT_SIZE + ro) * IN_SIZE + s0 + s4;
        *(uint2*)(g_kT_hi + off) = make_uint2(pack2(h[0], h[1]), pack2(h[2], h[3]));
        *(uint2*)(g_kT_lo + off) = make_uint2(pack2(l[0], l[1]), pack2(l[2], l[3]));
    }
}

// ---------------------------------------------------------------------------
// Kernel 5: attention: D[d,o] = Σ_s xT[d,s]·(uK)T[o,s]; att = v_o·D.
// CTA = (d-tile 128, n). M=128(d) N=64(o) K=1024(s), 16 chunks of 64.
// ---------------------------------------------------------------------------
__global__ __launch_bounds__(256) void attn_mma() {
    extern __shared__ char dyn[];
    __nv_bfloat16* Ah = (__nv_bfloat16*)(dyn + OFF_AH);
    __nv_bfloat16* Al = (__nv_bfloat16*)(dyn + OFF_AL);
    __nv_bfloat16* Bh = (__nv_bfloat16*)(dyn + OFF_BH);
    __nv_bfloat16* Bl = (__nv_bfloat16*)(dyn + OFF_BL);
    __shared__ float s_v[OUT_SIZE];

    int tid = threadIdx.x, lane = tid & 31, wid = tid >> 5;
    int wm = wid & 3, wn = wid >> 2;
    int n = blockIdx.y, b = n >> 2, h = n & 3;
    int d0 = blockIdx.x * 128;

    if (tid < OUT_SIZE) s_v[tid] = g_v[(size_t)n * OUT_SIZE + tid];

    const __nv_bfloat16* xh = g_xT_hi + ((size_t)b * IN_DIM + d0) * IN_SIZE;
    const __nv_bfloat16* xl = g_xT_lo + ((size_t)b * IN_DIM + d0) * IN_SIZE;
    const __nv_bfloat16* kh = g_kT_hi + (size_t)n * OUT_SIZE * IN_SIZE;
    const __nv_bfloat16* kl = g_kT_lo + (size_t)n * OUT_SIZE * IN_SIZE;

    uint32_t aBaseH = smem_u32(Ah) + ((wm * 32 + (lane & 15)) * RS + (lane >> 4) * 8) * 2;
    uint32_t aBaseL = aBaseH + (OFF_AL - OFF_AH);
    uint32_t bBaseH = smem_u32(Bh) + ((wn * 32 + (lane & 7)) * RS + ((lane >> 3) & 1) * 8) * 2;
    uint32_t bBaseL = bBaseH + (OFF_BL - OFF_BH);

    float c[2][4][4];
    #pragma unroll
    for (int f = 0; f < 2; ++f)
        #pragma unroll
        for (int g = 0; g < 4; ++g)
            #pragma unroll
            for (int q = 0; q < 4; ++q) c[f][g][q] = 0.f;

    for (int ch = 0; ch < 16; ++ch) {
        int s0 = ch * 64;
        // A: 128 d-rows x 64 s, straight bf16 copies (8-elem uint4)
        #pragma unroll
        for (int i = 0; i < 4; ++i) {
            int vi = i * 256 + tid;
            int row = vi >> 3, cu = vi & 7;
            size_t goff = (size_t)row * IN_SIZE + s0 + cu * 8;
            int off = row * RS + cu * 8;
            *(uint4*)(Ah + off) = *(const uint4*)(xh + goff);
            *(uint4*)(Al + off) = *(const uint4*)(xl + goff);
        }
        // B: 64 o-rows x 64 s
        #pragma unroll
        for (int i = 0; i < 2; ++i) {
            int vi = i * 256 + tid;
            int row = vi >> 3, cu = vi & 7;
            size_t goff = (size_t)row * IN_SIZE + s0 + cu * 8;
            int off = row * RS + cu * 8;
            *(uint4*)(Bh + off) = *(const uint4*)(kh + goff);
            *(uint4*)(Bl + off) = *(const uint4*)(kl + goff);
        }
        __syncthreads();
        #pragma unroll
        for (int ks = 0; ks < 4; ++ks) {
            uint32_t ah[2][4], al[2][4], bh[4][2], bl[4][2];
            #pragma unroll
            for (int f = 0; f < 2; ++f) {
                uint32_t o = (uint32_t)(f * 16 * RS + ks * 16) * 2;
                ldsm4(ah[f], aBaseH + o);
                ldsm4(al[f], aBaseL + o);
            }
            #pragma unroll
            for (int g = 0; g < 4; ++g) {
                uint32_t o = (uint32_t)(g * 8 * RS + ks * 16) * 2;
                ldsm2(bh[g], bBaseH + o);
                ldsm2(bl[g], bBaseL + o);
            }
            #pragma unroll
            for (int f = 0; f < 2; ++f)
                #pragma unroll
                for (int g = 0; g < 4; ++g) {
                    mma16816(c[f][g], ah[f], bh[g]);
                    mma16816(c[f][g], ah[f], bl[g]);
                    mma16816(c[f][g], al[f], bh[g]);
                }
        }
        __syncthreads();
    }

    // Epilogue: att[b][o][h*256+d] = v[o] * D[d][o]
    #pragma unroll
    for (int f = 0; f < 2; ++f) {
        int d = d0 + wm * 32 + f * 16 + (lane >> 2);
        #pragma unroll
        for (int g = 0; g < 4; ++g) {
            int o = wn * 32 + g * 8 + (lane & 3) * 2;
            float* base0 = g_att + ((size_t)b * OUT_SIZE + o) * HID + (size_t)h * IN_DIM;
            base0[d]           = s_v[o] * c[f][g][0];
            base0[HID + d]     = s_v[o + 1] * c[f][g][1];
            base0[d + 8]       = s_v[o] * c[f][g][2];
            base0[HID + d + 8] = s_v[o + 1] * c[f][g][3];
        }
    }
}

// ---------------------------------------------------------------------------
// Kernel 6: out = relu(att @ lin_wᵀ + lin_b)
// ---------------------------------------------------------------------------
__global__ __launch_bounds__(256) void linear_kernel(const float* __restrict__ lw,
                                                     const float* __restrict__ lb,
                                                     float* __restrict__ out) {
    const int BM = 64, BN = 64, BK = 32;
    __shared__ float As[BK][BM + 1];
    __shared__ float Bs[BK][BN + 1];

    int m0 = blockIdx.x * BM;
    int n0 = blockIdx.y * BN;
    int tid = threadIdx.x;
    int trow = tid >> 4, tcol = tid & 15;
    int lrow = tid >> 3;
    int lcol = (tid & 7) * 4;

    float acc[4][4];
    #pragma unroll
    for (int i = 0; i < 4; ++i)
        #pragma unroll
        for (int j = 0; j < 4; ++j) acc[i][j] = 0.f;

    for (int k0 = 0; k0 < HID; k0 += BK) {
        #pragma unroll
        for (int p = 0; p < 2; ++p) {
            float4 v = *(const float4*)(g_att + (size_t)(m0 + lrow + p * 32) * HID + k0 + lcol);
            As[lcol + 0][lrow + p * 32] = v.x;
            As[lcol + 1][lrow + p * 32] = v.y;
            As[lcol + 2][lrow + p * 32] = v.z;
            As[lcol + 3][lrow + p * 32] = v.w;
            float4 w = *(const float4*)(lw + (size_t)(n0 + lrow + p * 32) * HID + k0 + lcol);
            Bs[lcol + 0][lrow + p * 32] = w.x;
            Bs[lcol + 1][lrow + p * 32] = w.y;
            Bs[lcol + 2][lrow + p * 32] = w.z;
            Bs[lcol + 3][lrow + p * 32] = w.w;
        }
        __syncthreads();
        #pragma unroll
        for (int k = 0; k < BK; ++k) {
            float a[4], bb[4];
            #pragma unroll
            for (int i = 0; i < 4; ++i) a[i] = As[k][trow * 4 + i];
            #pragma unroll
            for (int j = 0; j < 4; ++j) bb[j] = Bs[k][tcol + 16 * j];
            #pragma unroll
            for (int i = 0; i < 4; ++i)
                #pragma unroll
                for (int j = 0; j < 4; ++j) acc[i][j] = fmaf(a[i], bb[j], acc[i][j]);
        }
        __syncthreads();
    }

    #pragma unroll
    for (int i = 0; i < 4; ++i) {
        int m = m0 + trow * 4 + i;
        #pragma unroll
        for (int j = 0; j < 4; ++j) {
            int nn = n0 + tcol + 16 * j;
            float r = acc[i][j] + lb[nn];
            out[(size_t)m * OUT_DIM + nn] = r > 0.f ? r : 0.f;
        }
    }
}

// ---------------------------------------------------------------------------
// Launch
// ---------------------------------------------------------------------------
extern "C" void kernel_launch(void* const* d_in, const int* in_sizes, int n_in,
                              void* d_out, int out_size) {
    const float* x    = (const float*)d_in[0];
    const int*   mask = (const int*)d_in[1];
    const float* W    = (const float*)d_in[2];
    const float* lw   = (const float*)d_in[3];
    const float* lb   = (const float*)d_in[4];
    float*       out  = (float*)d_out;

    cudaFuncSetAttribute(gemm_k_mma, cudaFuncAttributeMaxDynamicSharedMemorySize, DSMEM_BYTES);
    cudaFuncSetAttribute(attn_mma,   cudaFuncAttributeMaxDynamicSharedMemorySize, DSMEM_BYTES);

    xsplit_kernel<<<dim3(IN_SIZE / 64, IN_DIM / 64, BATCH), 256>>>(x);
    gemm_k_mma<<<dim3(IN_SIZE / 128, NMAT), 256, DSMEM_BYTES>>>(x, W);
    sinkhorn_kernel<<<NMAT, 1024>>>(mask);
    kut_kernel<<<dim3(IN_SIZE / 64, NMAT), 256>>>();
    attn_mma<<<dim3(IN_DIM / 128, NMAT), 256, DSMEM_BYTES>>>();
    linear_kernel<<<dim3(BATCH * OUT_SIZE / 64, OUT_DIM / 64), 256>>>(lw, lb, out);
}